// round 4
// baseline (speedup 1.0000x reference)
#include <cuda_runtime.h>
#include <math.h>

#define BB 4
#define SS 2048
#define HD 1024
#define NH 8
#define DK 128
#define WA 67
#define BH (BB*NH)
#define NROWS (BH*SS)
#define OUT1_ELEMS (BB*SS*NH*WA)
#define WPAD 68
#define SCALE 0.08838834764831845f

// ---------------- scratch (device globals; no allocation allowed) ----------------
__device__ float g_Q[BB*SS*HD];
__device__ float g_K[BB*SS*HD];
__device__ float g_V[BB*SS*HD];
__device__ float g_cD[NROWS*WA];

// db4 filters, pre-reversed:  g[t] = DEC[7-t]
__constant__ float REV_LO[8] = {
    0.23037781330885523f,  0.7148465705525415f,   0.6308807679295904f,
   -0.02798376941698385f, -0.18703481171888114f,  0.030841381835986965f,
    0.032883011666982945f,-0.010597401784997278f };
__constant__ float REV_HI[8] = {
   -0.010597401784997278f,-0.032883011666982945f, 0.030841381835986965f,
    0.18703481171888114f, -0.02798376941698385f, -0.6308807679295904f,
    0.7148465705525415f,  -0.23037781330885523f };

// ---------------- Kernel 1: QKV GEMM  C = x @ W^T ----------------
// grid: (N/64, M/64, 3), block 256. Tiles 64x64x16, 4x4 per-thread.
__global__ __launch_bounds__(256) void qkv_gemm(
    const float* __restrict__ x,
    const float* __restrict__ Wq,
    const float* __restrict__ Wk,
    const float* __restrict__ Wv)
{
    __shared__ float As[16*WPAD];
    __shared__ float Bs[16*WPAD];

    const int mat = blockIdx.z;
    const float* __restrict__ Wm = (mat == 0) ? Wq : ((mat == 1) ? Wk : Wv);
    float* __restrict__ C = (mat == 0) ? g_Q : ((mat == 1) ? g_K : g_V);

    const int m0 = blockIdx.y * 64;
    const int n0 = blockIdx.x * 64;
    const int t  = threadIdx.x;
    const int tx = t & 15;
    const int ty = t >> 4;
    const int lrow = t >> 2;
    const int lkq  = (t & 3) * 4;

    float acc[4][4] = {};

    for (int kt = 0; kt < HD; kt += 16) {
        float4 av = *(const float4*)&x [(m0 + lrow)*HD + kt + lkq];
        float4 wv = *(const float4*)&Wm[(n0 + lrow)*HD + kt + lkq];
        As[(lkq+0)*WPAD + lrow] = av.x;
        As[(lkq+1)*WPAD + lrow] = av.y;
        As[(lkq+2)*WPAD + lrow] = av.z;
        As[(lkq+3)*WPAD + lrow] = av.w;
        Bs[(lkq+0)*WPAD + lrow] = wv.x;
        Bs[(lkq+1)*WPAD + lrow] = wv.y;
        Bs[(lkq+2)*WPAD + lrow] = wv.z;
        Bs[(lkq+3)*WPAD + lrow] = wv.w;
        __syncthreads();
        #pragma unroll
        for (int k = 0; k < 16; k++) {
            float4 a = *(const float4*)&As[k*WPAD + 4*ty];
            float4 b = *(const float4*)&Bs[k*WPAD + 4*tx];
            acc[0][0] += a.x*b.x; acc[0][1] += a.x*b.y; acc[0][2] += a.x*b.z; acc[0][3] += a.x*b.w;
            acc[1][0] += a.y*b.x; acc[1][1] += a.y*b.y; acc[1][2] += a.y*b.z; acc[1][3] += a.y*b.w;
            acc[2][0] += a.z*b.x; acc[2][1] += a.z*b.y; acc[2][2] += a.z*b.z; acc[2][3] += a.z*b.w;
            acc[3][0] += a.w*b.x; acc[3][1] += a.w*b.y; acc[3][2] += a.w*b.z; acc[3][3] += a.w*b.w;
        }
        __syncthreads();
    }

    #pragma unroll
    for (int i = 0; i < 4; i++) {
        float4 st = make_float4(acc[i][0], acc[i][1], acc[i][2], acc[i][3]);
        *(float4*)&C[(m0 + 4*ty + i)*HD + n0 + 4*tx] = st;
    }
}

// ---------------- Kernel 2: db4 DWT of V along dk ----------------
// one warp per (b,h,s) row.  cA -> d_out second half (raw layout), cD -> g_cD.
__global__ __launch_bounds__(256) void dwt_kernel(float* __restrict__ outA)
{
    __shared__ float sv[8][128];
    const int warp = threadIdx.x >> 5;
    const int lane = threadIdx.x & 31;
    const int rid  = blockIdx.x * 8 + warp;        // (b*8+h)*2048 + s
    const int b = rid >> 14;
    const int h = (rid >> 11) & 7;
    const int s = rid & 2047;

    float4 v4 = *(const float4*)&g_V[(b*SS + s)*HD + h*DK + lane*4];
    sv[warp][lane*4+0] = v4.x;
    sv[warp][lane*4+1] = v4.y;
    sv[warp][lane*4+2] = v4.z;
    sv[warp][lane*4+3] = v4.w;
    __syncwarp();

    for (int j = lane; j < WA; j += 32) {
        float alo = 0.f, ahi = 0.f;
        #pragma unroll
        for (int tt = 0; tt < 8; tt++) {
            int i  = 2*j + tt;
            int vi = (i <= 5) ? (5 - i) : ((i <= 133) ? (i - 6) : (261 - i));
            float e = sv[warp][vi];
            alo += e * REV_LO[tt];
            ahi += e * REV_HI[tt];
        }
        outA[rid*WA + j] = alo;
        g_cD[rid*WA + j] = ahi;
    }
}

// ---------------- Kernel 3: flash attention, P @ cD ----------------
// grid (S/64, B*H), block 256. Online softmax over 32 key chunks of 64.
__global__ __launch_bounds__(256, 2) void attn_kernel(float* __restrict__ out1)
{
    extern __shared__ float sm[];
    float* Qt   = sm;                    // [128][WPAD]  d-major
    float* Kt   = Qt  + 128*WPAD;        // [128][WPAD]
    float* cDs  = Kt  + 128*WPAD;        // [64][WPAD]   key-major
    float* St   = cDs + 64*WPAD;         // [64 keys][WPAD rows] scores->probs in place
    float* sm_m = St  + 64*WPAD;
    float* sm_l = sm_m + 64;
    float* sm_f = sm_l + 64;

    const int t  = threadIdx.x;
    const int tx = t & 15;
    const int ty = t >> 4;
    const int bh = blockIdx.y;
    const int b  = bh >> 3;
    const int h  = bh & 7;
    const int q0 = blockIdx.x * 64;

    // Q tile (transposed: Qt[d][row])
    for (int i = t; i < 64*32; i += 256) {
        int row = i >> 5, dq = (i & 31) * 4;
        float4 v = *(const float4*)&g_Q[(b*SS + q0 + row)*HD + h*DK + dq];
        Qt[(dq+0)*WPAD + row] = v.x;
        Qt[(dq+1)*WPAD + row] = v.y;
        Qt[(dq+2)*WPAD + row] = v.z;
        Qt[(dq+3)*WPAD + row] = v.w;
    }
    if (t < 64) { sm_m[t] = -1e30f; sm_l[t] = 0.f; }

    float O[4][5] = {};
    int cload[5];
    #pragma unroll
    for (int cc = 0; cc < 5; cc++) {
        int c = tx + 16*cc;
        cload[cc] = (c < WA) ? c : (WA - 1);
    }
    __syncthreads();

    for (int k0 = 0; k0 < SS; k0 += 64) {
        // load K chunk transposed + cD chunk
        for (int i = t; i < 64*32; i += 256) {
            int row = i >> 5, dq = (i & 31) * 4;
            float4 v = *(const float4*)&g_K[(b*SS + k0 + row)*HD + h*DK + dq];
            Kt[(dq+0)*WPAD + row] = v.x;
            Kt[(dq+1)*WPAD + row] = v.y;
            Kt[(dq+2)*WPAD + row] = v.z;
            Kt[(dq+3)*WPAD + row] = v.w;
        }
        for (int i = t; i < 64*WA; i += 256) {
            int row = i / WA, w = i - row*WA;
            cDs[row*WPAD + w] = g_cD[(bh*SS + k0 + row)*WA + w];
        }
        __syncthreads();

        // Phase A: 64x64 scores, 4x4 per thread
        float acc[4][4] = {};
        #pragma unroll 8
        for (int d = 0; d < 128; d++) {
            float4 a = *(const float4*)&Qt[d*WPAD + 4*ty];
            float4 k = *(const float4*)&Kt[d*WPAD + 4*tx];
            acc[0][0] += a.x*k.x; acc[0][1] += a.x*k.y; acc[0][2] += a.x*k.z; acc[0][3] += a.x*k.w;
            acc[1][0] += a.y*k.x; acc[1][1] += a.y*k.y; acc[1][2] += a.y*k.z; acc[1][3] += a.y*k.w;
            acc[2][0] += a.z*k.x; acc[2][1] += a.z*k.y; acc[2][2] += a.z*k.z; acc[2][3] += a.z*k.w;
            acc[3][0] += a.w*k.x; acc[3][1] += a.w*k.y; acc[3][2] += a.w*k.z; acc[3][3] += a.w*k.w;
        }
        #pragma unroll
        for (int jj = 0; jj < 4; jj++)
            #pragma unroll
            for (int ii = 0; ii < 4; ii++)
                St[(4*tx + jj)*WPAD + 4*ty + ii] = acc[ii][jj];
        __syncthreads();

        // Phase B: online softmax, in-place exp (4 threads per row)
        {
            const int r = t >> 2, sub = t & 3;
            float sv[16];
            #pragma unroll
            for (int jj = 0; jj < 16; jj++)
                sv[jj] = St[(sub + 4*jj)*WPAD + r] * SCALE;
            float mloc = sv[0];
            #pragma unroll
            for (int jj = 1; jj < 16; jj++) mloc = fmaxf(mloc, sv[jj]);
            mloc = fmaxf(mloc, __shfl_xor_sync(0xffffffffu, mloc, 1));
            mloc = fmaxf(mloc, __shfl_xor_sync(0xffffffffu, mloc, 2));
            float mold = sm_m[r];
            float mnew = fmaxf(mold, mloc);
            float fac  = __expf(mold - mnew);
            float ssum = 0.f;
            #pragma unroll
            for (int jj = 0; jj < 16; jj++) {
                float p = __expf(sv[jj] - mnew);
                St[(sub + 4*jj)*WPAD + r] = p;
                ssum += p;
            }
            ssum += __shfl_xor_sync(0xffffffffu, ssum, 1);
            ssum += __shfl_xor_sync(0xffffffffu, ssum, 2);
            if (sub == 0) {
                sm_m[r] = mnew;
                sm_l[r] = sm_l[r]*fac + ssum;
                sm_f[r] = fac;
            }
        }
        __syncthreads();

        // Phase C: O = O*fac + P @ cD
        #pragma unroll
        for (int i = 0; i < 4; i++) {
            float f = sm_f[4*ty + i];
            #pragma unroll
            for (int cc = 0; cc < 5; cc++) O[i][cc] *= f;
        }
        #pragma unroll 4
        for (int j = 0; j < 64; j++) {
            float4 p = *(const float4*)&St[j*WPAD + 4*ty];
            float cdv[5];
            #pragma unroll
            for (int cc = 0; cc < 5; cc++) cdv[cc] = cDs[j*WPAD + cload[cc]];
            #pragma unroll
            for (int cc = 0; cc < 5; cc++) {
                O[0][cc] += p.x * cdv[cc];
                O[1][cc] += p.y * cdv[cc];
                O[2][cc] += p.z * cdv[cc];
                O[3][cc] += p.w * cdv[cc];
            }
        }
        __syncthreads();
    }

    // epilogue: divide by l, store out1[b][q][h*67+c]
    #pragma unroll
    for (int i = 0; i < 4; i++) {
        float linv = 1.f / sm_l[4*ty + i];
        int q = q0 + 4*ty + i;
        #pragma unroll
        for (int cc = 0; cc < 5; cc++) {
            int c = tx + 16*cc;
            if (c < WA)
                out1[(b*SS + q)*(NH*WA) + h*WA + c] = O[i][cc] * linv;
        }
    }
}

// ---------------- launch ----------------
extern "C" void kernel_launch(void* const* d_in, const int* in_sizes, int n_in,
                              void* d_out, int out_size)
{
    const float* x  = (const float*)d_in[0];
    const float* Wq = (const float*)d_in[1];
    const float* Wk = (const float*)d_in[2];
    const float* Wv = (const float*)d_in[3];
    float* out = (float*)d_out;

    (void)in_sizes; (void)n_in; (void)out_size;

    dim3 gg(HD/64, (BB*SS)/64, 3);
    qkv_gemm<<<gg, 256>>>(x, Wq, Wk, Wv);

    dwt_kernel<<<NROWS/8, 256>>>(out + OUT1_ELEMS);

    const int smem_bytes = (128*WPAD*2 + 64*WPAD*2 + 3*64) * (int)sizeof(float);
    cudaFuncSetAttribute(attn_kernel, cudaFuncAttributeMaxDynamicSharedMemorySize, smem_bytes);
    attn_kernel<<<dim3(SS/64, BH), 256, smem_bytes>>>(out);
}

// round 6
// speedup vs baseline: 1.9369x; 1.9369x over previous
#include <cuda_runtime.h>
#include <cuda_bf16.h>
#include <math.h>
#include <stdint.h>

#define BB 4
#define SS 2048
#define HD 1024
#define NH 8
#define DK 128
#define WA 67
#define BH (BB*NH)
#define NROWS (BH*SS)
#define OUT1_ELEMS (BB*SS*NH*WA)
#define WPAD 68
#define SCALE 0.08838834764831845f

// ---------------- scratch (device globals; no allocation allowed) ----------------
__device__ float g_V[BB*SS*HD];
__device__ float g_cD[NROWS*WA];
__device__ __nv_bfloat16 g_Xhi[BB*SS*HD];
__device__ __nv_bfloat16 g_Xlo[BB*SS*HD];
__device__ __nv_bfloat16 g_Whi[3*HD*HD];
__device__ __nv_bfloat16 g_Wlo[3*HD*HD];
__device__ __nv_bfloat16 g_Qhi[BB*SS*HD];
__device__ __nv_bfloat16 g_Qlo[BB*SS*HD];
__device__ __nv_bfloat16 g_Khi[BB*SS*HD];
__device__ __nv_bfloat16 g_Klo[BB*SS*HD];

// db4 filters, pre-reversed:  g[t] = DEC[7-t]
__constant__ float REV_LO[8] = {
    0.23037781330885523f,  0.7148465705525415f,   0.6308807679295904f,
   -0.02798376941698385f, -0.18703481171888114f,  0.030841381835986965f,
    0.032883011666982945f,-0.010597401784997278f };
__constant__ float REV_HI[8] = {
   -0.010597401784997278f,-0.032883011666982945f, 0.030841381835986965f,
    0.18703481171888114f, -0.02798376941698385f, -0.6308807679295904f,
    0.7148465705525415f,  -0.23037781330885523f };

// ---------------- helpers ----------------
__device__ __forceinline__ uint32_t smem_u32(const void* p) {
    uint32_t a;
    asm("{ .reg .u64 t; cvta.to.shared.u64 t, %1; cvt.u32.u64 %0, t; }" : "=r"(a) : "l"(p));
    return a;
}
__device__ __forceinline__ void cp16(uint32_t s, const void* g) {
    asm volatile("cp.async.cg.shared.global [%0], [%1], 16;" :: "r"(s), "l"(g));
}
__device__ __forceinline__ void mma16816(float* d,
    uint32_t a0, uint32_t a1, uint32_t a2, uint32_t a3, uint32_t b0, uint32_t b1) {
    asm volatile(
        "mma.sync.aligned.m16n8k16.row.col.f32.bf16.bf16.f32 "
        "{%0,%1,%2,%3}, {%4,%5,%6,%7}, {%8,%9}, {%0,%1,%2,%3};"
        : "+f"(d[0]), "+f"(d[1]), "+f"(d[2]), "+f"(d[3])
        : "r"(a0), "r"(a1), "r"(a2), "r"(a3), "r"(b0), "r"(b1));
}

// ---------------- Kernel 0: fp32 -> bf16 hi/lo split ----------------
__global__ __launch_bounds__(256) void split_x(const float* __restrict__ src)
{
    int i = blockIdx.x * blockDim.x + threadIdx.x;   // float4 index
    float4 v = *(const float4*)(src + 4*i);
    __nv_bfloat16 h0 = __float2bfloat16_rn(v.x), h1 = __float2bfloat16_rn(v.y);
    __nv_bfloat16 h2 = __float2bfloat16_rn(v.z), h3 = __float2bfloat16_rn(v.w);
    __nv_bfloat16 l0 = __float2bfloat16_rn(v.x - __bfloat162float(h0));
    __nv_bfloat16 l1 = __float2bfloat16_rn(v.y - __bfloat162float(h1));
    __nv_bfloat16 l2 = __float2bfloat16_rn(v.z - __bfloat162float(h2));
    __nv_bfloat16 l3 = __float2bfloat16_rn(v.w - __bfloat162float(h3));
    ((__nv_bfloat162*)g_Xhi)[2*i]   = __nv_bfloat162(h0, h1);
    ((__nv_bfloat162*)g_Xhi)[2*i+1] = __nv_bfloat162(h2, h3);
    ((__nv_bfloat162*)g_Xlo)[2*i]   = __nv_bfloat162(l0, l1);
    ((__nv_bfloat162*)g_Xlo)[2*i+1] = __nv_bfloat162(l2, l3);
}
__global__ __launch_bounds__(256) void split_w(const float* __restrict__ src, int mat)
{
    int i = blockIdx.x * blockDim.x + threadIdx.x;
    size_t base = (size_t)mat * HD * HD / 2;          // bfloat162 index base
    float4 v = *(const float4*)(src + 4*i);
    __nv_bfloat16 h0 = __float2bfloat16_rn(v.x), h1 = __float2bfloat16_rn(v.y);
    __nv_bfloat16 h2 = __float2bfloat16_rn(v.z), h3 = __float2bfloat16_rn(v.w);
    __nv_bfloat16 l0 = __float2bfloat16_rn(v.x - __bfloat162float(h0));
    __nv_bfloat16 l1 = __float2bfloat16_rn(v.y - __bfloat162float(h1));
    __nv_bfloat16 l2 = __float2bfloat16_rn(v.z - __bfloat162float(h2));
    __nv_bfloat16 l3 = __float2bfloat16_rn(v.w - __bfloat162float(h3));
    ((__nv_bfloat162*)g_Whi)[base + 2*i]   = __nv_bfloat162(h0, h1);
    ((__nv_bfloat162*)g_Whi)[base + 2*i+1] = __nv_bfloat162(h2, h3);
    ((__nv_bfloat162*)g_Wlo)[base + 2*i]   = __nv_bfloat162(l0, l1);
    ((__nv_bfloat162*)g_Wlo)[base + 2*i+1] = __nv_bfloat162(l2, l3);
}

// ---------------- Kernel 1: QKV GEMM via mma.sync bf16-split ----------------
#define KS 32
#define NST (HD/KS)
#define ARRB (128*80)
#define STAGEB (4*ARRB)

__global__ __launch_bounds__(256, 2) void qkv_mma()
{
    extern __shared__ char smem[];
    const int t = threadIdx.x, lane = t & 31, wid = t >> 5;
    const int wm = wid & 1, wn = wid >> 1;
    const int g = lane >> 2, qd = lane & 3;
    const int mat = blockIdx.z;
    const int m0 = blockIdx.y * 128, n0 = blockIdx.x * 128;
    const __nv_bfloat16* __restrict__ Bhp = g_Whi + (size_t)mat * HD * HD;
    const __nv_bfloat16* __restrict__ Blp = g_Wlo + (size_t)mat * HD * HD;
    uint32_t sb = smem_u32(smem);

    float acc[4][4][4] = {};

    auto stage = [&](int s, int b) {
        int kt = s * KS;
        uint32_t base = sb + b * STAGEB;
        #pragma unroll
        for (int i = 0; i < 2; i++) {
            int c = t + i * 256;
            int row = c >> 2, seg = c & 3;
            uint32_t so = row * 80 + seg * 16;
            size_t ga = (size_t)(m0 + row) * HD + kt + seg * 8;
            size_t gb = (size_t)(n0 + row) * HD + kt + seg * 8;
            cp16(base + so,          g_Xhi + ga);
            cp16(base + ARRB + so,   g_Xlo + ga);
            cp16(base + 2*ARRB + so, Bhp + gb);
            cp16(base + 3*ARRB + so, Blp + gb);
        }
        asm volatile("cp.async.commit_group;" ::: "memory");
    };

    stage(0, 0);
    int buf = 0;
    for (int s = 0; s < NST; s++) {
        if (s + 1 < NST) {
            stage(s + 1, buf ^ 1);
            asm volatile("cp.async.wait_group 1;" ::: "memory");
        } else {
            asm volatile("cp.async.wait_group 0;" ::: "memory");
        }
        __syncthreads();

        const uint32_t* AH = (const uint32_t*)(smem + buf*STAGEB);
        const uint32_t* AL = (const uint32_t*)(smem + buf*STAGEB + ARRB);
        const uint32_t* BHm = (const uint32_t*)(smem + buf*STAGEB + 2*ARRB);
        const uint32_t* BLm = (const uint32_t*)(smem + buf*STAGEB + 3*ARRB);

        #pragma unroll
        for (int ks = 0; ks < 2; ks++) {
            const int c2 = ks * 8 + qd;
            uint32_t bhf[4][2], blf[4][2];
            #pragma unroll
            for (int nt = 0; nt < 4; nt++) {
                int n = wn * 32 + nt * 8 + g;
                bhf[nt][0] = BHm[n*20 + c2];  bhf[nt][1] = BHm[n*20 + c2 + 4];
                blf[nt][0] = BLm[n*20 + c2];  blf[nt][1] = BLm[n*20 + c2 + 4];
            }
            #pragma unroll
            for (int mt = 0; mt < 4; mt++) {
                int r = wm * 64 + mt * 16 + g;
                uint32_t ah0 = AH[r*20 + c2],       ah1 = AH[(r+8)*20 + c2];
                uint32_t ah2 = AH[r*20 + c2 + 4],   ah3 = AH[(r+8)*20 + c2 + 4];
                uint32_t al0 = AL[r*20 + c2],       al1 = AL[(r+8)*20 + c2];
                uint32_t al2 = AL[r*20 + c2 + 4],   al3 = AL[(r+8)*20 + c2 + 4];
                #pragma unroll
                for (int nt = 0; nt < 4; nt++) {
                    mma16816(acc[mt][nt], ah0, ah1, ah2, ah3, bhf[nt][0], bhf[nt][1]);
                    mma16816(acc[mt][nt], al0, al1, al2, al3, bhf[nt][0], bhf[nt][1]);
                    mma16816(acc[mt][nt], ah0, ah1, ah2, ah3, blf[nt][0], blf[nt][1]);
                }
            }
        }
        __syncthreads();
        buf ^= 1;
    }

    if (mat == 2) {
        #pragma unroll
        for (int mt = 0; mt < 4; mt++) {
            int r = m0 + wm*64 + mt*16 + g;
            #pragma unroll
            for (int nt = 0; nt < 4; nt++) {
                int c = n0 + wn*32 + nt*8 + 2*qd;
                *(float2*)&g_V[(size_t)r*HD + c]     = make_float2(acc[mt][nt][0], acc[mt][nt][1]);
                *(float2*)&g_V[(size_t)(r+8)*HD + c] = make_float2(acc[mt][nt][2], acc[mt][nt][3]);
            }
        }
    } else {
        __nv_bfloat16* Hp = mat ? g_Khi : g_Qhi;
        __nv_bfloat16* Lp = mat ? g_Klo : g_Qlo;
        #pragma unroll
        for (int mt = 0; mt < 4; mt++) {
            int r = m0 + wm*64 + mt*16 + g;
            #pragma unroll
            for (int nt = 0; nt < 4; nt++) {
                int c = n0 + wn*32 + nt*8 + 2*qd;
                #pragma unroll
                for (int half = 0; half < 2; half++) {
                    float v0 = acc[mt][nt][2*half], v1 = acc[mt][nt][2*half+1];
                    __nv_bfloat16 h0 = __float2bfloat16_rn(v0);
                    __nv_bfloat16 h1 = __float2bfloat16_rn(v1);
                    __nv_bfloat16 l0 = __float2bfloat16_rn(v0 - __bfloat162float(h0));
                    __nv_bfloat16 l1 = __float2bfloat16_rn(v1 - __bfloat162float(h1));
                    size_t off = (size_t)(r + 8*half)*HD + c;
                    *(__nv_bfloat162*)&Hp[off] = __nv_bfloat162(h0, h1);
                    *(__nv_bfloat162*)&Lp[off] = __nv_bfloat162(l0, l1);
                }
            }
        }
    }
}

// ---------------- Kernel 2: db4 DWT of V along dk ----------------
__global__ __launch_bounds__(256) void dwt_kernel(float* __restrict__ outA)
{
    __shared__ float sv[8][128];
    const int warp = threadIdx.x >> 5;
    const int lane = threadIdx.x & 31;
    const int rid  = blockIdx.x * 8 + warp;
    const int b = rid >> 14;
    const int h = (rid >> 11) & 7;
    const int s = rid & 2047;

    float4 v4 = *(const float4*)&g_V[(b*SS + s)*HD + h*DK + lane*4];
    sv[warp][lane*4+0] = v4.x;
    sv[warp][lane*4+1] = v4.y;
    sv[warp][lane*4+2] = v4.z;
    sv[warp][lane*4+3] = v4.w;
    __syncwarp();

    for (int j = lane; j < WA; j += 32) {
        float alo = 0.f, ahi = 0.f;
        #pragma unroll
        for (int tt = 0; tt < 8; tt++) {
            int i  = 2*j + tt;
            int vi = (i <= 5) ? (5 - i) : ((i <= 133) ? (i - 6) : (261 - i));
            float e = sv[warp][vi];
            alo += e * REV_LO[tt];
            ahi += e * REV_HI[tt];
        }
        outA[rid*WA + j] = alo;
        g_cD[rid*WA + j] = ahi;
    }
}

// ---------------- Kernel 3: flash attention; scores via mma.sync ----------------
#define QH_OFF 0
#define QL_OFF 17408
#define KH_OFF 34816
#define KL_OFF 52224
#define CD_OFF 69632
#define ST_OFF 87040
#define ML_OFF 104448
#define ATTN_SMEM (ML_OFF + 3*64*4)

__global__ __launch_bounds__(256, 2) void attn_kernel(float* __restrict__ out1)
{
    extern __shared__ char smem[];
    const uint32_t* QH = (const uint32_t*)(smem + QH_OFF);
    const uint32_t* QL = (const uint32_t*)(smem + QL_OFF);
    const uint32_t* KH = (const uint32_t*)(smem + KH_OFF);
    const uint32_t* KL = (const uint32_t*)(smem + KL_OFF);
    float* cDs  = (float*)(smem + CD_OFF);
    float* St   = (float*)(smem + ST_OFF);
    float* sm_m = (float*)(smem + ML_OFF);
    float* sm_l = sm_m + 64;
    float* sm_f = sm_l + 64;

    const int t  = threadIdx.x;
    const int lane = t & 31, wid = t >> 5;
    const int g = lane >> 2, qd = lane & 3;
    const int tx = t & 15;
    const int ty = t >> 4;
    const int bh = blockIdx.y;
    const int b  = bh >> 3;
    const int h  = bh & 7;
    const int q0 = blockIdx.x * 64;

    for (int i = t; i < 64*16; i += 256) {
        int row = i >> 4, seg = i & 15;
        size_t go = (size_t)(b*SS + q0 + row)*HD + h*DK + seg*8;
        *(uint4*)(smem + QH_OFF + row*272 + seg*16) = *(const uint4*)(g_Qhi + go);
        *(uint4*)(smem + QL_OFF + row*272 + seg*16) = *(const uint4*)(g_Qlo + go);
    }
    if (t < 64) { sm_m[t] = -1e30f; sm_l[t] = 0.f; }

    float O[4][5] = {};
    int cload[5];
    #pragma unroll
    for (int cc = 0; cc < 5; cc++) {
        int c = tx + 16*cc;
        cload[cc] = (c < WA) ? c : (WA - 1);
    }
    __syncthreads();

    for (int k0 = 0; k0 < SS; k0 += 64) {
        for (int i = t; i < 64*16; i += 256) {
            int row = i >> 4, seg = i & 15;
            size_t go = (size_t)(b*SS + k0 + row)*HD + h*DK + seg*8;
            *(uint4*)(smem + KH_OFF + row*272 + seg*16) = *(const uint4*)(g_Khi + go);
            *(uint4*)(smem + KL_OFF + row*272 + seg*16) = *(const uint4*)(g_Klo + go);
        }
        for (int i = t; i < 64*WA; i += 256) {
            int row = i / WA, w = i - row*WA;
            cDs[row*WPAD + w] = g_cD[(bh*SS + k0 + row)*WA + w];
        }
        __syncthreads();

        {
            float acc[4][4] = {};
            #pragma unroll
            for (int ks = 0; ks < 8; ks++) {
                const int c2 = ks * 8 + qd;
                int n = wid * 8 + g;
                uint32_t bh0 = KH[n*68 + c2], bh1 = KH[n*68 + c2 + 4];
                uint32_t bl0 = KL[n*68 + c2], bl1 = KL[n*68 + c2 + 4];
                #pragma unroll
                for (int mt = 0; mt < 4; mt++) {
                    int r = mt*16 + g;
                    uint32_t ah0 = QH[r*68 + c2],     ah1 = QH[(r+8)*68 + c2];
                    uint32_t ah2 = QH[r*68 + c2 + 4], ah3 = QH[(r+8)*68 + c2 + 4];
                    uint32_t al0 = QL[r*68 + c2],     al1 = QL[(r+8)*68 + c2];
                    uint32_t al2 = QL[r*68 + c2 + 4], al3 = QL[(r+8)*68 + c2 + 4];
                    mma16816(acc[mt], ah0, ah1, ah2, ah3, bh0, bh1);
                    mma16816(acc[mt], al0, al1, al2, al3, bh0, bh1);
                    mma16816(acc[mt], ah0, ah1, ah2, ah3, bl0, bl1);
                }
            }
            #pragma unroll
            for (int mt = 0; mt < 4; mt++) {
                int q   = mt*16 + g;
                int key = wid*8 + 2*qd;
                St[key*WPAD + q]         = acc[mt][0];
                St[(key+1)*WPAD + q]     = acc[mt][1];
                St[key*WPAD + q + 8]     = acc[mt][2];
                St[(key+1)*WPAD + q + 8] = acc[mt][3];
            }
        }
        __syncthreads();

        {
            const int r = t >> 2, sub = t & 3;
            float sv[16];
            #pragma unroll
            for (int jj = 0; jj < 16; jj++)
                sv[jj] = St[(sub + 4*jj)*WPAD + r] * SCALE;
            float mloc = sv[0];
            #pragma unroll
            for (int jj = 1; jj < 16; jj++) mloc = fmaxf(mloc, sv[jj]);
            mloc = fmaxf(mloc, __shfl_xor_sync(0xffffffffu, mloc, 1));
            mloc = fmaxf(mloc, __shfl_xor_sync(0xffffffffu, mloc, 2));
            float mold = sm_m[r];
            float mnew = fmaxf(mold, mloc);
            float fac  = __expf(mold - mnew);
            float ssum = 0.f;
            #pragma unroll
            for (int jj = 0; jj < 16; jj++) {
                float p = __expf(sv[jj] - mnew);
                St[(sub + 4*jj)*WPAD + r] = p;
                ssum += p;
            }
            ssum += __shfl_xor_sync(0xffffffffu, ssum, 1);
            ssum += __shfl_xor_sync(0xffffffffu, ssum, 2);
            if (sub == 0) {
                sm_m[r] = mnew;
                sm_l[r] = sm_l[r]*fac + ssum;
                sm_f[r] = fac;
            }
        }
        __syncthreads();

        #pragma unroll
        for (int i = 0; i < 4; i++) {
            float f = sm_f[4*ty + i];
            #pragma unroll
            for (int cc = 0; cc < 5; cc++) O[i][cc] *= f;
        }
        #pragma unroll 4
        for (int j = 0; j < 64; j++) {
            float4 p = *(const float4*)&St[j*WPAD + 4*ty];
            float cdv[5];
            #pragma unroll
            for (int cc = 0; cc < 5; cc++) cdv[cc] = cDs[j*WPAD + cload[cc]];
            #pragma unroll
            for (int cc = 0; cc < 5; cc++) {
                O[0][cc] += p.x * cdv[cc];
                O[1][cc] += p.y * cdv[cc];
                O[2][cc] += p.z * cdv[cc];
                O[3][cc] += p.w * cdv[cc];
            }
        }
        __syncthreads();
    }

    #pragma unroll
    for (int i = 0; i < 4; i++) {
        float linv = 1.f / sm_l[4*ty + i];
        int q = q0 + 4*ty + i;
        #pragma unroll
        for (int cc = 0; cc < 5; cc++) {
            int c = tx + 16*cc;
            if (c < WA)
                out1[(b*SS + q)*(NH*WA) + h*WA + c] = O[i][cc] * linv;
        }
    }
}

// ---------------- launch ----------------
extern "C" void kernel_launch(void* const* d_in, const int* in_sizes, int n_in,
                              void* d_out, int out_size)
{
    const float* x  = (const float*)d_in[0];
    const float* Wq = (const float*)d_in[1];
    const float* Wk = (const float*)d_in[2];
    const float* Wv = (const float*)d_in[3];
    float* out = (float*)d_out;

    (void)in_sizes; (void)n_in; (void)out_size;

    split_x<<<(BB*SS*HD/4 + 255)/256, 256>>>(x);
    split_w<<<(HD*HD/4 + 255)/256, 256>>>(Wq, 0);
    split_w<<<(HD*HD/4 + 255)/256, 256>>>(Wk, 1);
    split_w<<<(HD*HD/4 + 255)/256, 256>>>(Wv, 2);

    cudaFuncSetAttribute(qkv_mma, cudaFuncAttributeMaxDynamicSharedMemorySize, 2*STAGEB);
    qkv_mma<<<dim3(HD/128, (BB*SS)/128, 3), 256, 2*STAGEB>>>();

    dwt_kernel<<<NROWS/8, 256>>>(out + OUT1_ELEMS);

    cudaFuncSetAttribute(attn_kernel, cudaFuncAttributeMaxDynamicSharedMemorySize, ATTN_SMEM);
    attn_kernel<<<dim3(SS/64, BH), 256, ATTN_SMEM>>>(out);
}

// round 7
// speedup vs baseline: 2.6351x; 1.3604x over previous
#include <cuda_runtime.h>
#include <cuda_bf16.h>
#include <math.h>
#include <stdint.h>

#define BB 4
#define SS 2048
#define HD 1024
#define NH 8
#define DK 128
#define WA 67
#define BH (BB*NH)
#define NROWS (BH*SS)
#define OUT1_ELEMS (BB*SS*NH*WA)
#define OW (NH*WA)
#define SCALE 0.08838834764831845f

// ---------------- scratch (device globals; no allocation allowed) ----------------
__device__ float g_V[BB*SS*HD];
__device__ float g_cD[NROWS*WA];
__device__ __nv_bfloat16 g_Xhi[BB*SS*HD];
__device__ __nv_bfloat16 g_Xlo[BB*SS*HD];
__device__ __nv_bfloat16 g_Whi[3*HD*HD];
__device__ __nv_bfloat16 g_Wlo[3*HD*HD];
__device__ __nv_bfloat16 g_Qhi[BB*SS*HD];
__device__ __nv_bfloat16 g_Qlo[BB*SS*HD];
__device__ __nv_bfloat16 g_Khi[BB*SS*HD];
__device__ __nv_bfloat16 g_Klo[BB*SS*HD];

// db4 filters, pre-reversed:  g[t] = DEC[7-t]
__constant__ float REV_LO[8] = {
    0.23037781330885523f,  0.7148465705525415f,   0.6308807679295904f,
   -0.02798376941698385f, -0.18703481171888114f,  0.030841381835986965f,
    0.032883011666982945f,-0.010597401784997278f };
__constant__ float REV_HI[8] = {
   -0.010597401784997278f,-0.032883011666982945f, 0.030841381835986965f,
    0.18703481171888114f, -0.02798376941698385f, -0.6308807679295904f,
    0.7148465705525415f,  -0.23037781330885523f };

// ---------------- helpers ----------------
__device__ __forceinline__ uint32_t smem_u32(const void* p) {
    uint32_t a;
    asm("{ .reg .u64 t; cvta.to.shared.u64 t, %1; cvt.u32.u64 %0, t; }" : "=r"(a) : "l"(p));
    return a;
}
__device__ __forceinline__ void cp16(uint32_t s, const void* g) {
    asm volatile("cp.async.cg.shared.global [%0], [%1], 16;" :: "r"(s), "l"(g));
}
__device__ __forceinline__ void mma16816(float* d,
    uint32_t a0, uint32_t a1, uint32_t a2, uint32_t a3, uint32_t b0, uint32_t b1) {
    asm volatile(
        "mma.sync.aligned.m16n8k16.row.col.f32.bf16.bf16.f32 "
        "{%0,%1,%2,%3}, {%4,%5,%6,%7}, {%8,%9}, {%0,%1,%2,%3};"
        : "+f"(d[0]), "+f"(d[1]), "+f"(d[2]), "+f"(d[3])
        : "r"(a0), "r"(a1), "r"(a2), "r"(a3), "r"(b0), "r"(b1));
}
__device__ __forceinline__ void ldm_x4(uint32_t* r, uint32_t addr) {
    asm volatile("ldmatrix.sync.aligned.m8n8.x4.shared.b16 {%0,%1,%2,%3}, [%4];"
        : "=r"(r[0]), "=r"(r[1]), "=r"(r[2]), "=r"(r[3]) : "r"(addr));
}
__device__ __forceinline__ void ldm_x2(uint32_t* r, uint32_t addr) {
    asm volatile("ldmatrix.sync.aligned.m8n8.x2.shared.b16 {%0,%1}, [%2];"
        : "=r"(r[0]), "=r"(r[1]) : "r"(addr));
}

// ---------------- Kernel 0: fp32 -> bf16 hi/lo split ----------------
__global__ __launch_bounds__(256) void split_x(const float* __restrict__ src)
{
    int i = blockIdx.x * blockDim.x + threadIdx.x;
    float4 v = *(const float4*)(src + 4*i);
    __nv_bfloat16 h0 = __float2bfloat16_rn(v.x), h1 = __float2bfloat16_rn(v.y);
    __nv_bfloat16 h2 = __float2bfloat16_rn(v.z), h3 = __float2bfloat16_rn(v.w);
    __nv_bfloat16 l0 = __float2bfloat16_rn(v.x - __bfloat162float(h0));
    __nv_bfloat16 l1 = __float2bfloat16_rn(v.y - __bfloat162float(h1));
    __nv_bfloat16 l2 = __float2bfloat16_rn(v.z - __bfloat162float(h2));
    __nv_bfloat16 l3 = __float2bfloat16_rn(v.w - __bfloat162float(h3));
    ((__nv_bfloat162*)g_Xhi)[2*i]   = __nv_bfloat162(h0, h1);
    ((__nv_bfloat162*)g_Xhi)[2*i+1] = __nv_bfloat162(h2, h3);
    ((__nv_bfloat162*)g_Xlo)[2*i]   = __nv_bfloat162(l0, l1);
    ((__nv_bfloat162*)g_Xlo)[2*i+1] = __nv_bfloat162(l2, l3);
}
__global__ __launch_bounds__(256) void split_w(const float* __restrict__ src, int mat)
{
    int i = blockIdx.x * blockDim.x + threadIdx.x;
    size_t base = (size_t)mat * HD * HD / 2;
    float4 v = *(const float4*)(src + 4*i);
    __nv_bfloat16 h0 = __float2bfloat16_rn(v.x), h1 = __float2bfloat16_rn(v.y);
    __nv_bfloat16 h2 = __float2bfloat16_rn(v.z), h3 = __float2bfloat16_rn(v.w);
    __nv_bfloat16 l0 = __float2bfloat16_rn(v.x - __bfloat162float(h0));
    __nv_bfloat16 l1 = __float2bfloat16_rn(v.y - __bfloat162float(h1));
    __nv_bfloat16 l2 = __float2bfloat16_rn(v.z - __bfloat162float(h2));
    __nv_bfloat16 l3 = __float2bfloat16_rn(v.w - __bfloat162float(h3));
    ((__nv_bfloat162*)g_Whi)[base + 2*i]   = __nv_bfloat162(h0, h1);
    ((__nv_bfloat162*)g_Whi)[base + 2*i+1] = __nv_bfloat162(h2, h3);
    ((__nv_bfloat162*)g_Wlo)[base + 2*i]   = __nv_bfloat162(l0, l1);
    ((__nv_bfloat162*)g_Wlo)[base + 2*i+1] = __nv_bfloat162(l2, l3);
}

// ---------------- Kernel 1: QKV GEMM via mma.sync + ldmatrix ----------------
#define KS 32
#define NST (HD/KS)
#define ARRB (128*80)
#define STAGEB (4*ARRB)

__global__ __launch_bounds__(256, 2) void qkv_mma()
{
    extern __shared__ char smem[];
    const int t = threadIdx.x, lane = t & 31, wid = t >> 5;
    const int wm = wid & 1, wn = wid >> 1;
    const int g = lane >> 2, qd = lane & 3;
    const int mat = blockIdx.z;
    const int m0 = blockIdx.y * 128, n0 = blockIdx.x * 128;
    const __nv_bfloat16* __restrict__ Bhp = g_Whi + (size_t)mat * HD * HD;
    const __nv_bfloat16* __restrict__ Blp = g_Wlo + (size_t)mat * HD * HD;
    uint32_t sb = smem_u32(smem);

    float acc[4][4][4] = {};

    // ldmatrix per-lane row/col offsets
    const uint32_t arow_off = (uint32_t)((wm*64 + (lane & 15)) * 80 + (lane >> 4) * 16);
    const uint32_t brow_off = (uint32_t)((wn*32 + (lane & 7) + ((lane >> 4) << 3)) * 80
                                         + ((lane >> 3) & 1) * 16);

    auto stage = [&](int s, int bsel) {
        int kt = s * KS;
        uint32_t base = sb + bsel * STAGEB;
        #pragma unroll
        for (int i = 0; i < 2; i++) {
            int c = t + i * 256;
            int row = c >> 2, seg = c & 3;
            uint32_t so = row * 80 + seg * 16;
            size_t ga = (size_t)(m0 + row) * HD + kt + seg * 8;
            size_t gb = (size_t)(n0 + row) * HD + kt + seg * 8;
            cp16(base + so,          g_Xhi + ga);
            cp16(base + ARRB + so,   g_Xlo + ga);
            cp16(base + 2*ARRB + so, Bhp + gb);
            cp16(base + 3*ARRB + so, Blp + gb);
        }
        asm volatile("cp.async.commit_group;" ::: "memory");
    };

    stage(0, 0);
    int buf = 0;
    for (int s = 0; s < NST; s++) {
        if (s + 1 < NST) {
            stage(s + 1, buf ^ 1);
            asm volatile("cp.async.wait_group 1;" ::: "memory");
        } else {
            asm volatile("cp.async.wait_group 0;" ::: "memory");
        }
        __syncthreads();

        uint32_t sbase = sb + buf * STAGEB;
        #pragma unroll
        for (int ks = 0; ks < 2; ks++) {
            uint32_t bh4[2][4], bl4[2][4];
            #pragma unroll
            for (int ntp = 0; ntp < 2; ntp++) {
                uint32_t baddr = sbase + 2*ARRB + brow_off + ntp*(16*80) + ks*32;
                ldm_x4(bh4[ntp], baddr);
                ldm_x4(bl4[ntp], baddr + ARRB);
            }
            #pragma unroll
            for (int mt = 0; mt < 4; mt++) {
                uint32_t aaddr = sbase + arow_off + mt*(16*80) + ks*32;
                uint32_t ah[4], al[4];
                ldm_x4(ah, aaddr);
                ldm_x4(al, aaddr + ARRB);
                #pragma unroll
                for (int nt = 0; nt < 4; nt++) {
                    uint32_t b0 = bh4[nt>>1][(nt&1)*2], b1 = bh4[nt>>1][(nt&1)*2+1];
                    uint32_t c0 = bl4[nt>>1][(nt&1)*2], c1 = bl4[nt>>1][(nt&1)*2+1];
                    mma16816(acc[mt][nt], ah[0],ah[1],ah[2],ah[3], b0, b1);
                    mma16816(acc[mt][nt], al[0],al[1],al[2],al[3], b0, b1);
                    mma16816(acc[mt][nt], ah[0],ah[1],ah[2],ah[3], c0, c1);
                }
            }
        }
        __syncthreads();
        buf ^= 1;
    }

    if (mat == 2) {
        #pragma unroll
        for (int mt = 0; mt < 4; mt++) {
            int r = m0 + wm*64 + mt*16 + g;
            #pragma unroll
            for (int nt = 0; nt < 4; nt++) {
                int c = n0 + wn*32 + nt*8 + 2*qd;
                *(float2*)&g_V[(size_t)r*HD + c]     = make_float2(acc[mt][nt][0], acc[mt][nt][1]);
                *(float2*)&g_V[(size_t)(r+8)*HD + c] = make_float2(acc[mt][nt][2], acc[mt][nt][3]);
            }
        }
    } else {
        __nv_bfloat16* Hp = mat ? g_Khi : g_Qhi;
        __nv_bfloat16* Lp = mat ? g_Klo : g_Qlo;
        #pragma unroll
        for (int mt = 0; mt < 4; mt++) {
            int r = m0 + wm*64 + mt*16 + g;
            #pragma unroll
            for (int nt = 0; nt < 4; nt++) {
                int c = n0 + wn*32 + nt*8 + 2*qd;
                #pragma unroll
                for (int half = 0; half < 2; half++) {
                    float v0 = acc[mt][nt][2*half], v1 = acc[mt][nt][2*half+1];
                    __nv_bfloat16 h0 = __float2bfloat16_rn(v0);
                    __nv_bfloat16 h1 = __float2bfloat16_rn(v1);
                    __nv_bfloat16 l0 = __float2bfloat16_rn(v0 - __bfloat162float(h0));
                    __nv_bfloat16 l1 = __float2bfloat16_rn(v1 - __bfloat162float(h1));
                    size_t off = (size_t)(r + 8*half)*HD + c;
                    *(__nv_bfloat162*)&Hp[off] = __nv_bfloat162(h0, h1);
                    *(__nv_bfloat162*)&Lp[off] = __nv_bfloat162(l0, l1);
                }
            }
        }
    }
}

// ---------------- Kernel 2: db4 DWT of V along dk ----------------
__global__ __launch_bounds__(256) void dwt_kernel(float* __restrict__ outA)
{
    __shared__ float sv[8][128];
    const int warp = threadIdx.x >> 5;
    const int lane = threadIdx.x & 31;
    const int rid  = blockIdx.x * 8 + warp;
    const int b = rid >> 14;
    const int h = (rid >> 11) & 7;
    const int s = rid & 2047;

    float4 v4 = *(const float4*)&g_V[(b*SS + s)*HD + h*DK + lane*4];
    sv[warp][lane*4+0] = v4.x;
    sv[warp][lane*4+1] = v4.y;
    sv[warp][lane*4+2] = v4.z;
    sv[warp][lane*4+3] = v4.w;
    __syncwarp();

    for (int j = lane; j < WA; j += 32) {
        float alo = 0.f, ahi = 0.f;
        #pragma unroll
        for (int tt = 0; tt < 8; tt++) {
            int i  = 2*j + tt;
            int vi = (i <= 5) ? (5 - i) : ((i <= 133) ? (i - 6) : (261 - i));
            float e = sv[warp][vi];
            alo += e * REV_LO[tt];
            ahi += e * REV_HI[tt];
        }
        outA[rid*WA + j] = alo;
        g_cD[rid*WA + j] = ahi;
    }
}

// ---------------- Kernel 3: flash attention, fully tensorized ----------------
// smem layout (bytes):
//   QH 0       QL 17408    KH 34816   KL 52224        (64 x 272B rows, 128 bf16 + pad)
//   CDH 69632  CDL 81152                               (80 x 144B rows: [w][key] bf16)
//   PH 92672   PL 101888                               (64 x 144B rows: [q][key] bf16)
//   St = 92672 (overlay on PH/PL; 64x68 f32, dead before PH/PL written)
//   ML 111104 (m/l/f, 3*64 f32)
#define QH_OFF 0
#define QL_OFF 17408
#define KH_OFF 34816
#define KL_OFF 52224
#define CDH_OFF 69632
#define CDL_OFF 81152
#define PH_OFF 92672
#define PL_OFF 101888
#define ST_OFF 92672
#define ML_OFF 111104
#define ATTN_SMEM (ML_OFF + 3*64*4)

__global__ __launch_bounds__(256, 2) void attn_kernel(float* __restrict__ out1)
{
    extern __shared__ char smem[];
    uint32_t sb = smem_u32(smem);
    float* St   = (float*)(smem + ST_OFF);
    __nv_bfloat16* PH  = (__nv_bfloat16*)(smem + PH_OFF);
    __nv_bfloat16* PL  = (__nv_bfloat16*)(smem + PL_OFF);
    __nv_bfloat16* CDH = (__nv_bfloat16*)(smem + CDH_OFF);
    __nv_bfloat16* CDL = (__nv_bfloat16*)(smem + CDL_OFF);
    float* sm_m = (float*)(smem + ML_OFF);
    float* sm_l = sm_m + 64;
    float* sm_f = sm_l + 64;

    const int t = threadIdx.x;
    const int lane = t & 31, wid = t >> 5;
    const int g = lane >> 2, qd = lane & 3;
    const int bh = blockIdx.y;
    const int b  = bh >> 3;
    const int h  = bh & 7;
    const int q0 = blockIdx.x * 64;

    // Phase C warp roles
    const int mtc = wid >> 1, nhc = wid & 1;

    // load Q tiles (hi/lo), 272B rows
    for (int i = t; i < 64*16; i += 256) {
        int row = i >> 4, seg = i & 15;
        size_t go = (size_t)(b*SS + q0 + row)*HD + h*DK + seg*8;
        *(uint4*)(smem + QH_OFF + row*272 + seg*16) = *(const uint4*)(g_Qhi + go);
        *(uint4*)(smem + QL_OFF + row*272 + seg*16) = *(const uint4*)(g_Qlo + go);
    }
    // zero CD pad rows 67..79 (13 rows x 36 words per array)
    for (int i = t; i < 13*36; i += 256) {
        ((uint32_t*)(smem + CDH_OFF + 67*144))[i] = 0;
        ((uint32_t*)(smem + CDL_OFF + 67*144))[i] = 0;
    }
    if (t < 64) { sm_m[t] = -1e30f; sm_l[t] = 0.f; }

    float O[5][4] = {};
    __syncthreads();

    for (int k0c = 0; k0c < SS; k0c += 64) {
        // load K chunk (cp.async) + cD chunk (convert + transpose)
        for (int i = t; i < 64*16; i += 256) {
            int row = i >> 4, seg = i & 15;
            size_t go = (size_t)(b*SS + k0c + row)*HD + h*DK + seg*8;
            cp16(sb + KH_OFF + row*272 + seg*16, g_Khi + go);
            cp16(sb + KL_OFF + row*272 + seg*16, g_Klo + go);
        }
        asm volatile("cp.async.commit_group;" ::: "memory");
        for (int i = t; i < 64*WA; i += 256) {
            int key = i / WA, w = i - key*WA;
            float v = g_cD[(size_t)(bh*SS + k0c + key)*WA + w];
            __nv_bfloat16 hv = __float2bfloat16_rn(v);
            __nv_bfloat16 lv = __float2bfloat16_rn(v - __bfloat162float(hv));
            CDH[w*72 + key] = hv;
            CDL[w*72 + key] = lv;
        }
        asm volatile("cp.async.wait_group 0;" ::: "memory");
        __syncthreads();

        // -------- Phase A: scores via mma + ldmatrix --------
        {
            float acc[4][4] = {};
            const uint32_t kbase = sb + KH_OFF
                + (uint32_t)((wid*8 + (lane & 7))*272 + ((lane >> 3) & 1)*16);
            const uint32_t qoff = (uint32_t)((lane & 15)*272 + (lane >> 4)*16);
            #pragma unroll
            for (int ks = 0; ks < 8; ks++) {
                uint32_t bhf[2], blf[2];
                ldm_x2(bhf, kbase + ks*32);
                ldm_x2(blf, kbase + ks*32 + (KL_OFF - KH_OFF));
                #pragma unroll
                for (int mt = 0; mt < 4; mt++) {
                    uint32_t qaddr = sb + QH_OFF + qoff + mt*(16*272) + ks*32;
                    uint32_t ah[4], al[4];
                    ldm_x4(ah, qaddr);
                    ldm_x4(al, qaddr + (QL_OFF - QH_OFF));
                    mma16816(acc[mt], ah[0],ah[1],ah[2],ah[3], bhf[0], bhf[1]);
                    mma16816(acc[mt], al[0],al[1],al[2],al[3], bhf[0], bhf[1]);
                    mma16816(acc[mt], ah[0],ah[1],ah[2],ah[3], blf[0], blf[1]);
                }
            }
            #pragma unroll
            for (int mt = 0; mt < 4; mt++) {
                int q   = mt*16 + g;
                int key = wid*8 + 2*qd;
                St[key*68 + q]         = acc[mt][0];
                St[(key+1)*68 + q]     = acc[mt][1];
                St[key*68 + q + 8]     = acc[mt][2];
                St[(key+1)*68 + q + 8] = acc[mt][3];
            }
        }
        __syncthreads();

        // -------- Phase B: online softmax; write P as bf16 hi/lo --------
        {
            const int r = t >> 2, sub = t & 3;
            float sv[16];
            #pragma unroll
            for (int jj = 0; jj < 16; jj++)
                sv[jj] = St[(sub + 4*jj)*68 + r] * SCALE;
            __syncthreads();     // St dead; PH/PL region now writable

            float mloc = sv[0];
            #pragma unroll
            for (int jj = 1; jj < 16; jj++) mloc = fmaxf(mloc, sv[jj]);
            mloc = fmaxf(mloc, __shfl_xor_sync(0xffffffffu, mloc, 1));
            mloc = fmaxf(mloc, __shfl_xor_sync(0xffffffffu, mloc, 2));
            float mold = sm_m[r];
            float mnew = fmaxf(mold, mloc);
            float fac  = __expf(mold - mnew);
            float ssum = 0.f;
            #pragma unroll
            for (int jj = 0; jj < 16; jj++) {
                float p = __expf(sv[jj] - mnew);
                int key = sub + 4*jj;
                __nv_bfloat16 ph = __float2bfloat16_rn(p);
                __nv_bfloat16 pl = __float2bfloat16_rn(p - __bfloat162float(ph));
                PH[r*72 + key] = ph;
                PL[r*72 + key] = pl;
                ssum += p;
            }
            ssum += __shfl_xor_sync(0xffffffffu, ssum, 1);
            ssum += __shfl_xor_sync(0xffffffffu, ssum, 2);
            if (sub == 0) {
                sm_m[r] = mnew;
                sm_l[r] = sm_l[r]*fac + ssum;
                sm_f[r] = fac;
            }
        }
        __syncthreads();

        // -------- Phase C: O = O*fac + P @ cD^T via mma + ldmatrix --------
        {
            float f0 = sm_f[mtc*16 + g];
            float f1 = sm_f[mtc*16 + 8 + g];
            #pragma unroll
            for (int nt = 0; nt < 5; nt++) {
                O[nt][0] *= f0; O[nt][1] *= f0;
                O[nt][2] *= f1; O[nt][3] *= f1;
            }
            const uint32_t pbase = sb + PH_OFF
                + (uint32_t)((mtc*16 + (lane & 15))*144 + (lane >> 4)*16);
            const uint32_t coff = (uint32_t)((lane & 7)*144 + ((lane >> 3) & 1)*16);
            #pragma unroll
            for (int ks = 0; ks < 4; ks++) {
                uint32_t pa[4], pl4[4];
                ldm_x4(pa,  pbase + ks*32);
                ldm_x4(pl4, pbase + ks*32 + (PL_OFF - PH_OFF));
                #pragma unroll
                for (int nt = 0; nt < 5; nt++) {
                    uint32_t caddr = sb + CDH_OFF + coff + (uint32_t)((nhc*5 + nt)*8*144) + ks*32;
                    uint32_t cbv[2], clv[2];
                    ldm_x2(cbv, caddr);
                    ldm_x2(clv, caddr + (CDL_OFF - CDH_OFF));
                    mma16816(O[nt], pa[0],pa[1],pa[2],pa[3],     cbv[0], cbv[1]);
                    mma16816(O[nt], pl4[0],pl4[1],pl4[2],pl4[3], cbv[0], cbv[1]);
                    mma16816(O[nt], pa[0],pa[1],pa[2],pa[3],     clv[0], clv[1]);
                }
            }
        }
        __syncthreads();
    }

    // epilogue: divide by l, store from fragments
    {
        float li0 = 1.f / sm_l[mtc*16 + g];
        float li1 = 1.f / sm_l[mtc*16 + 8 + g];
        int qa = q0 + mtc*16 + g;
        int qb = qa + 8;
        #pragma unroll
        for (int nt = 0; nt < 5; nt++) {
            int w0 = (nhc*5 + nt)*8 + 2*qd;
            if (w0 < WA) {
                out1[(size_t)(b*SS + qa)*OW + h*WA + w0] = O[nt][0]*li0;
                out1[(size_t)(b*SS + qb)*OW + h*WA + w0] = O[nt][2]*li1;
            }
            if (w0 + 1 < WA) {
                out1[(size_t)(b*SS + qa)*OW + h*WA + w0 + 1] = O[nt][1]*li0;
                out1[(size_t)(b*SS + qb)*OW + h*WA + w0 + 1] = O[nt][3]*li1;
            }
        }
    }
}

// ---------------- launch ----------------
extern "C" void kernel_launch(void* const* d_in, const int* in_sizes, int n_in,
                              void* d_out, int out_size)
{
    const float* x  = (const float*)d_in[0];
    const float* Wq = (const float*)d_in[1];
    const float* Wk = (const float*)d_in[2];
    const float* Wv = (const float*)d_in[3];
    float* out = (float*)d_out;

    (void)in_sizes; (void)n_in; (void)out_size;

    split_x<<<(BB*SS*HD/4 + 255)/256, 256>>>(x);
    split_w<<<(HD*HD/4 + 255)/256, 256>>>(Wq, 0);
    split_w<<<(HD*HD/4 + 255)/256, 256>>>(Wk, 1);
    split_w<<<(HD*HD/4 + 255)/256, 256>>>(Wv, 2);

    cudaFuncSetAttribute(qkv_mma, cudaFuncAttributeMaxDynamicSharedMemorySize, 2*STAGEB);
    qkv_mma<<<dim3(HD/128, (BB*SS)/128, 3), 256, 2*STAGEB>>>();

    dwt_kernel<<<NROWS/8, 256>>>(out + OUT1_ELEMS);

    cudaFuncSetAttribute(attn_kernel, cudaFuncAttributeMaxDynamicSharedMemorySize, ATTN_SMEM);
    attn_kernel<<<dim3(SS/64, BH), 256, ATTN_SMEM>>>(out);
}

// round 9
// speedup vs baseline: 3.5222x; 1.3367x over previous
#include <cuda_runtime.h>
#include <cuda_bf16.h>
#include <math.h>
#include <stdint.h>

#define BB 4
#define SS 2048
#define HD 1024
#define NH 8
#define DK 128
#define WA 67
#define BH (BB*NH)
#define NROWS (BH*SS)
#define OUT1_ELEMS (BB*SS*NH*WA)
#define OW (NH*WA)
#define SCALE 0.08838834764831845f

// ---------------- scratch (device globals; no allocation allowed) ----------------
__device__ float g_V[BB*SS*HD];
__device__ __nv_bfloat16 g_cDh[BH*80*SS];     // transposed: [bh][w(80, zero-padded)][s]
__device__ __nv_bfloat16 g_cDl[BH*80*SS];
__device__ __nv_bfloat16 g_Xhi[BB*SS*HD];
__device__ __nv_bfloat16 g_Xlo[BB*SS*HD];
__device__ __nv_bfloat16 g_Whi[3*HD*HD];
__device__ __nv_bfloat16 g_Wlo[3*HD*HD];
__device__ __nv_bfloat16 g_Qhi[BB*SS*HD];
__device__ __nv_bfloat16 g_Qlo[BB*SS*HD];
__device__ __nv_bfloat16 g_Khi[BB*SS*HD];
__device__ __nv_bfloat16 g_Klo[BB*SS*HD];

// db4 filters, pre-reversed:  g[t] = DEC[7-t]
__constant__ float REV_LO[8] = {
    0.23037781330885523f,  0.7148465705525415f,   0.6308807679295904f,
   -0.02798376941698385f, -0.18703481171888114f,  0.030841381835986965f,
    0.032883011666982945f,-0.010597401784997278f };
__constant__ float REV_HI[8] = {
   -0.010597401784997278f,-0.032883011666982945f, 0.030841381835986965f,
    0.18703481171888114f, -0.02798376941698385f, -0.6308807679295904f,
    0.7148465705525415f,  -0.23037781330885523f };

// ---------------- helpers ----------------
__device__ __forceinline__ uint32_t smem_u32(const void* p) {
    uint32_t a;
    asm("{ .reg .u64 t; cvta.to.shared.u64 t, %1; cvt.u32.u64 %0, t; }" : "=r"(a) : "l"(p));
    return a;
}
__device__ __forceinline__ void cp16(uint32_t s, const void* g) {
    asm volatile("cp.async.cg.shared.global [%0], [%1], 16;" :: "r"(s), "l"(g));
}
__device__ __forceinline__ void mma16816(float* d,
    uint32_t a0, uint32_t a1, uint32_t a2, uint32_t a3, uint32_t b0, uint32_t b1) {
    asm volatile(
        "mma.sync.aligned.m16n8k16.row.col.f32.bf16.bf16.f32 "
        "{%0,%1,%2,%3}, {%4,%5,%6,%7}, {%8,%9}, {%0,%1,%2,%3};"
        : "+f"(d[0]), "+f"(d[1]), "+f"(d[2]), "+f"(d[3])
        : "r"(a0), "r"(a1), "r"(a2), "r"(a3), "r"(b0), "r"(b1));
}
__device__ __forceinline__ void ldm_x4(uint32_t* r, uint32_t addr) {
    asm volatile("ldmatrix.sync.aligned.m8n8.x4.shared.b16 {%0,%1,%2,%3}, [%4];"
        : "=r"(r[0]), "=r"(r[1]), "=r"(r[2]), "=r"(r[3]) : "r"(addr));
}
__device__ __forceinline__ uint32_t pack_bf16x2(float lo, float hi) {
    uint32_t r;
    asm("cvt.rn.bf16x2.f32 %0, %1, %2;" : "=r"(r) : "f"(hi), "f"(lo));
    return r;
}
// split two fp32 into packed bf16x2 hi + residual-lo
__device__ __forceinline__ void split2(float p0, float p1, uint32_t& h, uint32_t& l) {
    h = pack_bf16x2(p0, p1);
    __nv_bfloat162 hv = *reinterpret_cast<__nv_bfloat162*>(&h);
    l = pack_bf16x2(p0 - __bfloat162float(hv.x), p1 - __bfloat162float(hv.y));
}

// ---------------- Kernel 0: fp32 -> bf16 hi/lo split ----------------
__global__ __launch_bounds__(256) void split_x(const float* __restrict__ src)
{
    int i = blockIdx.x * blockDim.x + threadIdx.x;
    float4 v = *(const float4*)(src + 4*i);
    __nv_bfloat16 h0 = __float2bfloat16_rn(v.x), h1 = __float2bfloat16_rn(v.y);
    __nv_bfloat16 h2 = __float2bfloat16_rn(v.z), h3 = __float2bfloat16_rn(v.w);
    __nv_bfloat16 l0 = __float2bfloat16_rn(v.x - __bfloat162float(h0));
    __nv_bfloat16 l1 = __float2bfloat16_rn(v.y - __bfloat162float(h1));
    __nv_bfloat16 l2 = __float2bfloat16_rn(v.z - __bfloat162float(h2));
    __nv_bfloat16 l3 = __float2bfloat16_rn(v.w - __bfloat162float(h3));
    ((__nv_bfloat162*)g_Xhi)[2*i]   = __nv_bfloat162(h0, h1);
    ((__nv_bfloat162*)g_Xhi)[2*i+1] = __nv_bfloat162(h2, h3);
    ((__nv_bfloat162*)g_Xlo)[2*i]   = __nv_bfloat162(l0, l1);
    ((__nv_bfloat162*)g_Xlo)[2*i+1] = __nv_bfloat162(l2, l3);
}
__global__ __launch_bounds__(256) void split_w(const float* __restrict__ src, int mat)
{
    int i = blockIdx.x * blockDim.x + threadIdx.x;
    size_t base = (size_t)mat * HD * HD / 2;
    float4 v = *(const float4*)(src + 4*i);
    __nv_bfloat16 h0 = __float2bfloat16_rn(v.x), h1 = __float2bfloat16_rn(v.y);
    __nv_bfloat16 h2 = __float2bfloat16_rn(v.z), h3 = __float2bfloat16_rn(v.w);
    __nv_bfloat16 l0 = __float2bfloat16_rn(v.x - __bfloat162float(h0));
    __nv_bfloat16 l1 = __float2bfloat16_rn(v.y - __bfloat162float(h1));
    __nv_bfloat16 l2 = __float2bfloat16_rn(v.z - __bfloat162float(h2));
    __nv_bfloat16 l3 = __float2bfloat16_rn(v.w - __bfloat162float(h3));
    ((__nv_bfloat162*)g_Whi)[base + 2*i]   = __nv_bfloat162(h0, h1);
    ((__nv_bfloat162*)g_Whi)[base + 2*i+1] = __nv_bfloat162(h2, h3);
    ((__nv_bfloat162*)g_Wlo)[base + 2*i]   = __nv_bfloat162(l0, l1);
    ((__nv_bfloat162*)g_Wlo)[base + 2*i+1] = __nv_bfloat162(l2, l3);
}

// ---------------- Kernel 1: QKV GEMM via mma.sync + ldmatrix ----------------
#define KS 32
#define NST (HD/KS)
#define ARRB (128*80)
#define STAGEB (4*ARRB)

__global__ __launch_bounds__(256, 2) void qkv_mma()
{
    extern __shared__ char smem[];
    const int t = threadIdx.x, lane = t & 31, wid = t >> 5;
    const int wm = wid & 1, wn = wid >> 1;
    const int g = lane >> 2, qd = lane & 3;
    const int mat = blockIdx.z;
    const int m0 = blockIdx.y * 128, n0 = blockIdx.x * 128;
    const __nv_bfloat16* __restrict__ Bhp = g_Whi + (size_t)mat * HD * HD;
    const __nv_bfloat16* __restrict__ Blp = g_Wlo + (size_t)mat * HD * HD;
    uint32_t sb = smem_u32(smem);

    float acc[4][4][4] = {};

    const uint32_t arow_off = (uint32_t)((wm*64 + (lane & 15)) * 80 + (lane >> 4) * 16);
    const uint32_t brow_off = (uint32_t)((wn*32 + (lane & 7) + ((lane >> 4) << 3)) * 80
                                         + ((lane >> 3) & 1) * 16);

    auto stage = [&](int s, int bsel) {
        int kt = s * KS;
        uint32_t base = sb + bsel * STAGEB;
        #pragma unroll
        for (int i = 0; i < 2; i++) {
            int c = t + i * 256;
            int row = c >> 2, seg = c & 3;
            uint32_t so = row * 80 + seg * 16;
            size_t ga = (size_t)(m0 + row) * HD + kt + seg * 8;
            size_t gb = (size_t)(n0 + row) * HD + kt + seg * 8;
            cp16(base + so,          g_Xhi + ga);
            cp16(base + ARRB + so,   g_Xlo + ga);
            cp16(base + 2*ARRB + so, Bhp + gb);
            cp16(base + 3*ARRB + so, Blp + gb);
        }
        asm volatile("cp.async.commit_group;" ::: "memory");
    };

    stage(0, 0);
    int buf = 0;
    for (int s = 0; s < NST; s++) {
        if (s + 1 < NST) {
            stage(s + 1, buf ^ 1);
            asm volatile("cp.async.wait_group 1;" ::: "memory");
        } else {
            asm volatile("cp.async.wait_group 0;" ::: "memory");
        }
        __syncthreads();

        uint32_t sbase = sb + buf * STAGEB;
        #pragma unroll
        for (int ks = 0; ks < 2; ks++) {
            uint32_t bh4[2][4], bl4[2][4];
            #pragma unroll
            for (int ntp = 0; ntp < 2; ntp++) {
                uint32_t baddr = sbase + 2*ARRB + brow_off + ntp*(16*80) + ks*32;
                ldm_x4(bh4[ntp], baddr);
                ldm_x4(bl4[ntp], baddr + ARRB);
            }
            #pragma unroll
            for (int mt = 0; mt < 4; mt++) {
                uint32_t aaddr = sbase + arow_off + mt*(16*80) + ks*32;
                uint32_t ah[4], al[4];
                ldm_x4(ah, aaddr);
                ldm_x4(al, aaddr + ARRB);
                #pragma unroll
                for (int nt = 0; nt < 4; nt++) {
                    uint32_t b0 = bh4[nt>>1][(nt&1)*2], b1 = bh4[nt>>1][(nt&1)*2+1];
                    uint32_t c0 = bl4[nt>>1][(nt&1)*2], c1 = bl4[nt>>1][(nt&1)*2+1];
                    mma16816(acc[mt][nt], ah[0],ah[1],ah[2],ah[3], b0, b1);
                    mma16816(acc[mt][nt], al[0],al[1],al[2],al[3], b0, b1);
                    mma16816(acc[mt][nt], ah[0],ah[1],ah[2],ah[3], c0, c1);
                }
            }
        }
        __syncthreads();
        buf ^= 1;
    }

    if (mat == 2) {
        #pragma unroll
        for (int mt = 0; mt < 4; mt++) {
            int r = m0 + wm*64 + mt*16 + g;
            #pragma unroll
            for (int nt = 0; nt < 4; nt++) {
                int c = n0 + wn*32 + nt*8 + 2*qd;
                *(float2*)&g_V[(size_t)r*HD + c]     = make_float2(acc[mt][nt][0], acc[mt][nt][1]);
                *(float2*)&g_V[(size_t)(r+8)*HD + c] = make_float2(acc[mt][nt][2], acc[mt][nt][3]);
            }
        }
    } else {
        __nv_bfloat16* Hp = mat ? g_Khi : g_Qhi;
        __nv_bfloat16* Lp = mat ? g_Klo : g_Qlo;
        #pragma unroll
        for (int mt = 0; mt < 4; mt++) {
            int r = m0 + wm*64 + mt*16 + g;
            #pragma unroll
            for (int nt = 0; nt < 4; nt++) {
                int c = n0 + wn*32 + nt*8 + 2*qd;
                #pragma unroll
                for (int half = 0; half < 2; half++) {
                    float v0 = acc[mt][nt][2*half], v1 = acc[mt][nt][2*half+1];
                    __nv_bfloat16 h0 = __float2bfloat16_rn(v0);
                    __nv_bfloat16 h1 = __float2bfloat16_rn(v1);
                    __nv_bfloat16 l0 = __float2bfloat16_rn(v0 - __bfloat162float(h0));
                    __nv_bfloat16 l1 = __float2bfloat16_rn(v1 - __bfloat162float(h1));
                    size_t off = (size_t)(r + 8*half)*HD + c;
                    *(__nv_bfloat162*)&Hp[off] = __nv_bfloat162(h0, h1);
                    *(__nv_bfloat162*)&Lp[off] = __nv_bfloat162(l0, l1);
                }
            }
        }
    }
}

// ---------------- Kernel 2: db4 DWT; cA -> out, cD -> transposed bf16 hi/lo ----------------
// block = (bh, 128 s rows). smem: sv [8][132] f32; cd tiles [80][130] bf16 (pitch 260B).
#define DW_SV 0
#define DW_CDH 4224
#define DW_CDL 25024
#define DWT_SMEM 45824

__global__ __launch_bounds__(256) void dwt_kernel(float* __restrict__ outA)
{
    extern __shared__ char dsm[];
    float* sv = (float*)(dsm + DW_SV);
    const int t = threadIdx.x, warp = t >> 5, lane = t & 31;
    const int bh = blockIdx.y, sblk = blockIdx.x;
    const int b = bh >> 3, h = bh & 7;

    // zero pad rows 67..79 of both cd tiles (13*130 bf16 = 845 words each)
    for (int i = t; i < 845; i += 256) {
        ((uint32_t*)(dsm + DW_CDH + 67*260))[i] = 0;
        ((uint32_t*)(dsm + DW_CDL + 67*260))[i] = 0;
    }

    for (int iter = 0; iter < 16; iter++) {
        int sl = iter*8 + warp;
        int s  = sblk*128 + sl;
        int rid = bh*SS + s;
        float4 v4 = *(const float4*)&g_V[(size_t)(b*SS + s)*HD + h*DK + lane*4];
        *(float4*)&sv[warp*132 + lane*4] = v4;
        __syncwarp();
        #pragma unroll
        for (int jj = 0; jj < 3; jj++) {
            int j = lane + jj*32;
            if (j < WA) {
                float alo = 0.f, ahi = 0.f;
                #pragma unroll
                for (int tt = 0; tt < 8; tt++) {
                    int i2 = 2*j + tt;
                    int vi = (i2 <= 5) ? (5 - i2) : ((i2 <= 133) ? (i2 - 6) : (261 - i2));
                    float e = sv[warp*132 + vi];
                    alo += e * REV_LO[tt];
                    ahi += e * REV_HI[tt];
                }
                outA[(size_t)rid*WA + j] = alo;
                __nv_bfloat16 hv = __float2bfloat16_rn(ahi);
                __nv_bfloat16 lv = __float2bfloat16_rn(ahi - __bfloat162float(hv));
                *(__nv_bfloat16*)(dsm + DW_CDH + j*260 + sl*2) = hv;
                *(__nv_bfloat16*)(dsm + DW_CDL + j*260 + sl*2) = lv;
            }
        }
        __syncwarp();
    }
    __syncthreads();

    // coalesced write-out: [bh][w][s]
    const size_t gbase = ((size_t)bh*80*SS + (size_t)sblk*128) >> 1;   // uint index
    for (int i = t; i < 80*64; i += 256) {
        int w = i >> 6, c = i & 63;
        uint32_t vh = *(uint32_t*)(dsm + DW_CDH + w*260 + c*4);
        uint32_t vl = *(uint32_t*)(dsm + DW_CDL + w*260 + c*4);
        ((uint32_t*)g_cDh)[gbase + (size_t)w*(SS/2) + c] = vh;
        ((uint32_t*)g_cDl)[gbase + (size_t)w*(SS/2) + c] = vl;
    }
}

// ---------------- Kernel 3: register-resident flash attention ----------------
// smem: QH 0, QL 17408, KH 34816, KL 52224 (64 x 272B rows);
//       CDH 69632, CDL 81152 (80 x 144B rows: [w][key]);
//       stats @92672: sm_mx[2][64], sm_sum[2][64] f32.  Obuf overlays KH at epilogue.
#define QH_OFF 0
#define QL_OFF 17408
#define KH_OFF 34816
#define KL_OFF 52224
#define CDH_OFF 69632
#define CDL_OFF 81152
#define STAT_OFF 92672
#define ATTN_SMEM (STAT_OFF + 1024)
#define OBUF_OFF KH_OFF

__global__ __launch_bounds__(256, 2) void attn_kernel(float* __restrict__ out1)
{
    extern __shared__ char smem[];
    uint32_t sb = smem_u32(smem);
    float* sm_mx  = (float*)(smem + STAT_OFF);
    float* sm_sum = sm_mx + 128;

    const int t = threadIdx.x;
    const int lane = t & 31, wid = t >> 5;
    const int g = lane >> 2, qd = lane & 3;
    const int qg = wid >> 1, kh = wid & 1;     // warp = (query-group, key-half)
    const int bh = blockIdx.y;
    const int b  = bh >> 3;
    const int h  = bh & 7;
    const int q0 = blockIdx.x * 64;
    const int r0 = qg*16 + g, r1 = r0 + 8;

    // load Q tiles (hi/lo)
    for (int i = t; i < 64*16; i += 256) {
        int row = i >> 4, seg = i & 15;
        size_t go = (size_t)(b*SS + q0 + row)*HD + h*DK + seg*8;
        *(uint4*)(smem + QH_OFF + row*272 + seg*16) = *(const uint4*)(g_Qhi + go);
        *(uint4*)(smem + QL_OFF + row*272 + seg*16) = *(const uint4*)(g_Qlo + go);
    }

    float O[10][4] = {};
    float m0 = -1e30f, m1 = -1e30f, l0 = 0.f, l1 = 0.f;

    const uint32_t qbase = sb + QH_OFF + (uint32_t)((qg*16 + (lane & 15))*272 + (lane >> 4)*16);
    const uint32_t kbase = sb + KH_OFF
        + (uint32_t)((kh*32 + (lane & 7) + ((lane >> 4) << 3))*272 + ((lane >> 3) & 1)*16);
    const uint32_t cbase = sb + CDH_OFF
        + (uint32_t)(((lane & 7) + ((lane >> 4) << 3))*144 + ((lane >> 3) & 1)*16 + kh*64);
    __syncthreads();

    for (int k0c = 0; k0c < SS; k0c += 64) {
        // K chunk + cD chunk via cp.async
        for (int i = t; i < 64*16; i += 256) {
            int row = i >> 4, seg = i & 15;
            size_t go = (size_t)(b*SS + k0c + row)*HD + h*DK + seg*8;
            cp16(sb + KH_OFF + row*272 + seg*16, g_Khi + go);
            cp16(sb + KL_OFF + row*272 + seg*16, g_Klo + go);
        }
        for (int i = t; i < 80*8; i += 256) {
            int w = i >> 3, c = i & 7;
            size_t go = (size_t)(bh*80 + w)*SS + k0c + c*8;
            cp16(sb + CDH_OFF + w*144 + c*16, g_cDh + go);
            cp16(sb + CDL_OFF + w*144 + c*16, g_cDl + go);
        }
        asm volatile("cp.async.commit_group;" ::: "memory");
        asm volatile("cp.async.wait_group 0;" ::: "memory");
        __syncthreads();

        // -------- Phase A: S (16q x 32k) in registers --------
        float acc[4][4] = {};
        #pragma unroll
        for (int kb = 0; kb < 8; kb++) {
            uint32_t ah[4], al[4], b0h[4], b1h[4], b0l[4], b1l[4];
            ldm_x4(ah, qbase + kb*32);
            ldm_x4(al, qbase + kb*32 + (QL_OFF - QH_OFF));
            ldm_x4(b0h, kbase + kb*32);
            ldm_x4(b1h, kbase + kb*32 + 16*272);
            ldm_x4(b0l, kbase + kb*32 + (KL_OFF - KH_OFF));
            ldm_x4(b1l, kbase + kb*32 + 16*272 + (KL_OFF - KH_OFF));
            #pragma unroll
            for (int nt = 0; nt < 4; nt++) {
                uint32_t h0 = (nt < 2) ? b0h[(nt&1)*2]   : b1h[(nt&1)*2];
                uint32_t h1 = (nt < 2) ? b0h[(nt&1)*2+1] : b1h[(nt&1)*2+1];
                uint32_t c0 = (nt < 2) ? b0l[(nt&1)*2]   : b1l[(nt&1)*2];
                uint32_t c1 = (nt < 2) ? b0l[(nt&1)*2+1] : b1l[(nt&1)*2+1];
                mma16816(acc[nt], ah[0],ah[1],ah[2],ah[3], h0, h1);
                mma16816(acc[nt], al[0],al[1],al[2],al[3], h0, h1);
                mma16816(acc[nt], ah[0],ah[1],ah[2],ah[3], c0, c1);
            }
        }

        // -------- Phase B: softmax in registers --------
        #pragma unroll
        for (int nt = 0; nt < 4; nt++)
            #pragma unroll
            for (int i2 = 0; i2 < 4; i2++) acc[nt][i2] *= SCALE;

        float mx0 = -1e30f, mx1 = -1e30f;
        #pragma unroll
        for (int nt = 0; nt < 4; nt++) {
            mx0 = fmaxf(mx0, fmaxf(acc[nt][0], acc[nt][1]));
            mx1 = fmaxf(mx1, fmaxf(acc[nt][2], acc[nt][3]));
        }
        mx0 = fmaxf(mx0, __shfl_xor_sync(0xffffffffu, mx0, 1));
        mx0 = fmaxf(mx0, __shfl_xor_sync(0xffffffffu, mx0, 2));
        mx1 = fmaxf(mx1, __shfl_xor_sync(0xffffffffu, mx1, 1));
        mx1 = fmaxf(mx1, __shfl_xor_sync(0xffffffffu, mx1, 2));
        if (qd == 0) { sm_mx[kh*64 + r0] = mx0; sm_mx[kh*64 + r1] = mx1; }
        __syncthreads();
        float mnew0 = fmaxf(m0, fmaxf(sm_mx[r0], sm_mx[64 + r0]));
        float mnew1 = fmaxf(m1, fmaxf(sm_mx[r1], sm_mx[64 + r1]));
        float fac0 = __expf(m0 - mnew0), fac1 = __expf(m1 - mnew1);
        float sum0 = 0.f, sum1 = 0.f;
        #pragma unroll
        for (int nt = 0; nt < 4; nt++) {
            acc[nt][0] = __expf(acc[nt][0] - mnew0);
            acc[nt][1] = __expf(acc[nt][1] - mnew0);
            acc[nt][2] = __expf(acc[nt][2] - mnew1);
            acc[nt][3] = __expf(acc[nt][3] - mnew1);
            sum0 += acc[nt][0] + acc[nt][1];
            sum1 += acc[nt][2] + acc[nt][3];
        }
        sum0 += __shfl_xor_sync(0xffffffffu, sum0, 1);
        sum0 += __shfl_xor_sync(0xffffffffu, sum0, 2);
        sum1 += __shfl_xor_sync(0xffffffffu, sum1, 1);
        sum1 += __shfl_xor_sync(0xffffffffu, sum1, 2);
        if (qd == 0) { sm_sum[kh*64 + r0] = sum0; sm_sum[kh*64 + r1] = sum1; }

        // convert P to bf16 hi/lo A-fragments in registers (S-frag == A-frag layout)
        uint32_t pah[2][4], pal[2][4];
        #pragma unroll
        for (int kbi = 0; kbi < 2; kbi++) {
            int na = 2*kbi, nb = na + 1;
            split2(acc[na][0], acc[na][1], pah[kbi][0], pal[kbi][0]);
            split2(acc[na][2], acc[na][3], pah[kbi][1], pal[kbi][1]);
            split2(acc[nb][0], acc[nb][1], pah[kbi][2], pal[kbi][2]);
            split2(acc[nb][2], acc[nb][3], pah[kbi][3], pal[kbi][3]);
        }
        __syncthreads();
        l0 = l0*fac0 + sm_sum[r0] + sm_sum[64 + r0];
        l1 = l1*fac1 + sm_sum[r1] + sm_sum[64 + r1];
        m0 = mnew0; m1 = mnew1;

        // -------- Phase C: O = O*fac + P @ cD^T --------
        #pragma unroll
        for (int nt = 0; nt < 10; nt++) {
            O[nt][0] *= fac0; O[nt][1] *= fac0;
            O[nt][2] *= fac1; O[nt][3] *= fac1;
        }
        #pragma unroll
        for (int kbi = 0; kbi < 2; kbi++) {
            #pragma unroll
            for (int ntp = 0; ntp < 5; ntp++) {
                uint32_t cb[4], cl[4];
                uint32_t ca = cbase + ntp*(16*144) + kbi*32;
                ldm_x4(cb, ca);
                ldm_x4(cl, ca + (CDL_OFF - CDH_OFF));
                mma16816(O[2*ntp],   pah[kbi][0],pah[kbi][1],pah[kbi][2],pah[kbi][3], cb[0], cb[1]);
                mma16816(O[2*ntp],   pal[kbi][0],pal[kbi][1],pal[kbi][2],pal[kbi][3], cb[0], cb[1]);
                mma16816(O[2*ntp],   pah[kbi][0],pah[kbi][1],pah[kbi][2],pah[kbi][3], cl[0], cl[1]);
                mma16816(O[2*ntp+1], pah[kbi][0],pah[kbi][1],pah[kbi][2],pah[kbi][3], cb[2], cb[3]);
                mma16816(O[2*ntp+1], pal[kbi][0],pal[kbi][1],pal[kbi][2],pal[kbi][3], cb[2], cb[3]);
                mma16816(O[2*ntp+1], pah[kbi][0],pah[kbi][1],pah[kbi][2],pah[kbi][3], cl[2], cl[3]);
            }
        }
        __syncthreads();
    }

    // -------- epilogue: merge kh halves, divide by l, store --------
    float* Obuf = (float*)(smem + OBUF_OFF);   // [64][81] f32, overlays dead K tiles
    if (kh == 1) {
        #pragma unroll
        for (int nt = 0; nt < 10; nt++) {
            int w = nt*8 + 2*qd;
            Obuf[r0*81 + w]     = O[nt][0];
            Obuf[r0*81 + w + 1] = O[nt][1];
            Obuf[r1*81 + w]     = O[nt][2];
            Obuf[r1*81 + w + 1] = O[nt][3];
        }
    }
    __syncthreads();
    if (kh == 0) {
        float li0 = 1.f / l0, li1 = 1.f / l1;
        int qa = q0 + r0, qb2 = q0 + r1;
        #pragma unroll
        for (int nt = 0; nt < 10; nt++) {
            int w = nt*8 + 2*qd;
            if (w < WA) {
                out1[(size_t)(b*SS + qa)*OW + h*WA + w]  = (O[nt][0] + Obuf[r0*81 + w])*li0;
                out1[(size_t)(b*SS + qb2)*OW + h*WA + w] = (O[nt][2] + Obuf[r1*81 + w])*li1;
            }
            if (w + 1 < WA) {
                out1[(size_t)(b*SS + qa)*OW + h*WA + w + 1]  = (O[nt][1] + Obuf[r0*81 + w + 1])*li0;
                out1[(size_t)(b*SS + qb2)*OW + h*WA + w + 1] = (O[nt][3] + Obuf[r1*81 + w + 1])*li1;
            }
        }
    }
}

// ---------------- launch ----------------
extern "C" void kernel_launch(void* const* d_in, const int* in_sizes, int n_in,
                              void* d_out, int out_size)
{
    const float* x  = (const float*)d_in[0];
    const float* Wq = (const float*)d_in[1];
    const float* Wk = (const float*)d_in[2];
    const float* Wv = (const float*)d_in[3];
    float* out = (float*)d_out;

    (void)in_sizes; (void)n_in; (void)out_size;

    split_x<<<(BB*SS*HD/4 + 255)/256, 256>>>(x);
    split_w<<<(HD*HD/4 + 255)/256, 256>>>(Wq, 0);
    split_w<<<(HD*HD/4 + 255)/256, 256>>>(Wk, 1);
    split_w<<<(HD*HD/4 + 255)/256, 256>>>(Wv, 2);

    cudaFuncSetAttribute(qkv_mma, cudaFuncAttributeMaxDynamicSharedMemorySize, 2*STAGEB);
    qkv_mma<<<dim3(HD/128, (BB*SS)/128, 3), 256, 2*STAGEB>>>();

    cudaFuncSetAttribute(dwt_kernel, cudaFuncAttributeMaxDynamicSharedMemorySize, DWT_SMEM);
    dwt_kernel<<<dim3(SS/128, BH), 256, DWT_SMEM>>>(out + OUT1_ELEMS);

    cudaFuncSetAttribute(attn_kernel, cudaFuncAttributeMaxDynamicSharedMemorySize, ATTN_SMEM);
    attn_kernel<<<dim3(SS/64, BH), 256, ATTN_SMEM>>>(out);
}